// round 4
// baseline (speedup 1.0000x reference)
#include <cuda_runtime.h>
#include <cuda_bf16.h>

#define D 8192
#define BATCH 4096

// d_z: after high-bit FWHT stages.  d_w: final weight row.
__device__ float d_z[D];
__device__ float d_w[D];

// ---------------------------------------------------------------------------
// stageA: g_tilde = g_mu + softplus(g_rho)*eps, scaled by s1[0], then the 6
// high-bit FWHT stages (element strides 128..4096 = g-bit strides 1..32 where
// element = g*128 + low). 8 blocks x 256 threads; block owns lows [b*16,b*16+16)
// for ALL 64 g.  All gmem traffic is float4 + segment-coalesced.
// ---------------------------------------------------------------------------
__global__ __launch_bounds__(256, 1)
void stageA_kernel(const float* __restrict__ s1,
                   const float* __restrict__ g_mu,
                   const float* __restrict__ g_rho,
                   const float* __restrict__ eps) {
#if __CUDA_ARCH__ >= 900
    cudaTriggerProgrammaticLaunchCompletion();
#endif
    __shared__ float sm[64 * 17];            // [g][low16], pad 17 vs bank conflicts
    const int t    = threadIdx.x;
    const int g    = t >> 2;                 // 0..63
    const int l4   = (t & 3) * 4;            // 0,4,8,12
    const int base = g * 128 + blockIdx.x * 16 + l4;

    const float s10 = __ldg(s1);
    float4 mu = *(const float4*)(g_mu  + base);
    float4 rh = *(const float4*)(g_rho + base);
    float4 ep = *(const float4*)(eps   + base);

    float v[4] = {rh.x, rh.y, rh.z, rh.w};
    float m[4] = {mu.x, mu.y, mu.z, mu.w};
    float e[4] = {ep.x, ep.y, ep.z, ep.w};
    #pragma unroll
    for (int i = 0; i < 4; i++) {
        float sp = fmaxf(v[i], 0.0f) + __logf(1.0f + __expf(-fabsf(v[i])));
        sm[g * 17 + l4 + i] = s10 * fmaf(sp, e[i], m[i]);   // fold s1[0] (linear)
    }
    __syncthreads();

    // 6 butterfly stages over g (strides 1,2,4,8,16,32 in g)
    #pragma unroll
    for (int s = 0; s < 6; s++) {
        const int h = 1 << s;
        #pragma unroll
        for (int bb = 0; bb < 2; bb++) {
            int bi = t + bb * 256;           // butterfly id 0..511
            int l  = bi & 15;
            int gi = bi >> 4;                // 0..31
            int ga = ((gi & ~(h - 1)) << 1) | (gi & (h - 1));
            int gb = ga + h;
            float a = sm[ga * 17 + l], b = sm[gb * 17 + l];
            sm[ga * 17 + l] = a + b;
            sm[gb * 17 + l] = a - b;
        }
        __syncthreads();
    }

    float4 o;
    o.x = sm[g * 17 + l4 + 0];
    o.y = sm[g * 17 + l4 + 1];
    o.z = sm[g * 17 + l4 + 2];
    o.w = sm[g * 17 + l4 + 3];
    *(float4*)(d_z + base) = o;
}

// ---------------------------------------------------------------------------
// stageB: low-bit stages (strides 1..64, confined to 128-groups) + s2 scale.
// One warp per 128-group: lane = bits 0..4 (shfl), k regs = bits 5..6.
// 16 blocks x 128 threads = 64 warps = 64 groups. Fully coalesced.
// (This decomposition is the one validated inside R3's outer kernel.)
// ---------------------------------------------------------------------------
__global__ __launch_bounds__(128, 1)
void stageB_kernel(const float* __restrict__ s2) {
#if __CUDA_ARCH__ >= 900
    cudaTriggerProgrammaticLaunchCompletion();
#endif
    const int lane = threadIdx.x & 31;
    const int r    = blockIdx.x * 4 + (threadIdx.x >> 5);   // 128-group 0..63
    const int base = r * 128 + lane;

    float s2v[4];
    #pragma unroll
    for (int k = 0; k < 4; k++) s2v[k] = __ldg(s2 + base + k * 32);

#if __CUDA_ARCH__ >= 900
    cudaGridDependencySynchronize();
#endif

    float rr[4];
    #pragma unroll
    for (int k = 0; k < 4; k++) rr[k] = d_z[base + k * 32];

    #pragma unroll
    for (int mmask = 1; mmask <= 16; mmask <<= 1) {
        const float sgn = (lane & mmask) ? -1.0f : 1.0f;
        #pragma unroll
        for (int k = 0; k < 4; k++) {
            float o = __shfl_xor_sync(0xffffffffu, rr[k], mmask);
            rr[k] = fmaf(sgn, rr[k], o);
        }
    }
    { // stride 32 (k bit 0)
        float a0 = rr[0], b0 = rr[1], a1 = rr[2], b1 = rr[3];
        rr[0] = a0 + b0; rr[1] = a0 - b0;
        rr[2] = a1 + b1; rr[3] = a1 - b1;
    }
    { // stride 64 (k bit 1)
        float a0 = rr[0], b0 = rr[2], a1 = rr[1], b1 = rr[3];
        rr[0] = a0 + b0; rr[2] = a0 - b0;
        rr[1] = a1 + b1; rr[3] = a1 - b1;
    }

    #pragma unroll
    for (int k = 0; k < 4; k++) d_w[base + k * 32] = s2v[k] * rr[k];
}

// ---------------------------------------------------------------------------
// outer: out[b][j] = x[b] * w[j]   (exact R1 body: measured 20.8us)
// grid (8, 256) x 256 threads, 16 rows/block, float4 streaming stores.
// PDL: x loads issued before the grid dependency sync.
// ---------------------------------------------------------------------------
#define ROWS_PER_BLOCK 16

__global__ __launch_bounds__(256)
void outer_kernel(const float* __restrict__ x, float* __restrict__ out) {
    const int jbase = blockIdx.x * 1024 + threadIdx.x * 4;
    const int b0    = blockIdx.y * ROWS_PER_BLOCK;

    float xs[ROWS_PER_BLOCK];
    #pragma unroll
    for (int q = 0; q < ROWS_PER_BLOCK; q++)
        xs[q] = __ldg(x + b0 + q);

#if __CUDA_ARCH__ >= 900
    cudaGridDependencySynchronize();
#endif

    const float4 w4 = *(const float4*)(d_w + jbase);

    #pragma unroll
    for (int q = 0; q < ROWS_PER_BLOCK; q++) {
        float xv = xs[q];
        float4 o = make_float4(xv * w4.x, xv * w4.y, xv * w4.z, xv * w4.w);
        // 134 MB output, never re-read -> streaming (evict-first) store
        __stcs((float4*)(out + (size_t)(b0 + q) * D + jbase), o);
    }
}

extern "C" void kernel_launch(void* const* d_in, const int* in_sizes, int n_in,
                              void* d_out, int out_size) {
    const float* x     = (const float*)d_in[0];
    const float* s1    = (const float*)d_in[1];
    const float* s2    = (const float*)d_in[2];
    const float* g_mu  = (const float*)d_in[3];
    const float* g_rho = (const float*)d_in[4];
    const float* eps   = (const float*)d_in[5];
    float* out = (float*)d_out;

    cudaLaunchAttribute attr;
    attr.id = cudaLaunchAttributeProgrammaticStreamSerialization;
    attr.val.programmaticStreamSerializationAllowed = 1;

    stageA_kernel<<<8, 256>>>(s1, g_mu, g_rho, eps);

    {
        cudaLaunchConfig_t cfg = {};
        cfg.gridDim = dim3(16, 1, 1);
        cfg.blockDim = dim3(128, 1, 1);
        cfg.stream = 0;
        cfg.attrs = &attr; cfg.numAttrs = 1;
        cudaLaunchKernelEx(&cfg, stageB_kernel, s2);
    }
    {
        cudaLaunchConfig_t cfg = {};
        cfg.gridDim = dim3(D / 1024, BATCH / ROWS_PER_BLOCK, 1);  // (8, 256)
        cfg.blockDim = dim3(256, 1, 1);
        cfg.stream = 0;
        cfg.attrs = &attr; cfg.numAttrs = 1;
        cudaLaunchKernelEx(&cfg, outer_kernel, x, out);
    }
}